// round 3
// baseline (speedup 1.0000x reference)
#include <cuda_runtime.h>
#include <cuda_bf16.h>

// ---------------------------------------------------------------------------
// HypernymVisual: h = relu(vfs)@W1 + b1 ; e = relu(h)@W2 + b2 ;
// scores[n,l] = -sqrt(sum_d relu(lv[l,d] - e[n,d])^2)
//
// Round 3: gemm1 rebuilt — 8-way K-split (512 blocks, occupancy), B tile
// stored pre-duplicated as f32x2 lane pairs (no pack movs in inner loop),
// double-buffered smem with register prefetch.
// ---------------------------------------------------------------------------

#define NV   256
#define DV   4096
#define DH   1024
#define DE   100
#define LL   20000
#define SPL1 8      // gemm1 K splits (512 cols each)

typedef unsigned long long u64;

__device__ float g_hp[SPL1][NV * DH];    // gemm1 K-split partials (no bias)
__device__ float g_ep[8][NV * DE];       // gemm2 K-split partials (no bias)

// ---- f32x2 helpers ---------------------------------------------------------
__device__ __forceinline__ u64 f2add(u64 a, u64 b) {
    u64 r; asm("add.rn.f32x2 %0,%1,%2;" : "=l"(r) : "l"(a), "l"(b)); return r;
}
__device__ __forceinline__ u64 f2fma(u64 a, u64 b, u64 c) {
    u64 r; asm("fma.rn.f32x2 %0,%1,%2,%3;" : "=l"(r) : "l"(a), "l"(b), "l"(c)); return r;
}
// packed ReLU: per-lane fmaxf(x,0) == signed int32 max(x,0) bitwise (IEEE754).
__device__ __forceinline__ u64 f2relu(u64 x) {
    u64 r;
    asm("{\n\t"
        ".reg .s32 lo, hi;\n\t"
        "mov.b64 {lo, hi}, %1;\n\t"
        "max.s32 lo, lo, 0;\n\t"
        "max.s32 hi, hi, 0;\n\t"
        "mov.b64 %0, {lo, hi};\n\t"
        "}" : "=l"(r) : "l"(x));
    return r;
}
__device__ __forceinline__ u64 fpack(float x, float y) {
    u64 r;
    unsigned lo = __float_as_uint(x), hi = __float_as_uint(y);
    asm("mov.b64 %0,{%1,%2};" : "=l"(r) : "r"(lo), "r"(hi));
    return r;
}
__device__ __forceinline__ float2 funpack(u64 a) {
    unsigned lo, hi;
    asm("mov.b64 {%0,%1},%2;" : "=r"(lo), "=r"(hi) : "l"(a));
    return make_float2(__uint_as_float(lo), __uint_as_float(hi));
}
__device__ __forceinline__ float fsqrt_ap(float x) {
    float r; asm("sqrt.approx.f32 %0,%1;" : "=f"(r) : "f"(x)); return r;
}

// ---------------------------------------------------------------------------
// GEMM1: g_hp[z] = relu(vfs) @ W1 over K-slice z (512 cols)
// 64x64 tile, 256 threads, thread tile 4m x 4n (f32x2 m-pairs).
// grid (16 n, 4 m, 8 z) = 512 blocks. Double-buffered smem.
// ---------------------------------------------------------------------------
__global__ __launch_bounds__(256) void gemm1_kernel(
    const float* __restrict__ vfs, const float* __restrict__ W1)
{
    __shared__ __align__(16) float As[2][16][68];   // transposed A: [k][m]
    __shared__ __align__(16) u64  Bs2[2][16][64];   // B dup pairs: [k][n]

    const int t  = threadIdx.x;
    const int m0 = blockIdx.y * 64;
    const int n0 = blockIdx.x * 64;
    const int kb0 = blockIdx.z * 512;

    const int tx = t & 15;                 // n-group
    const int ty = t >> 4;                 // m-group (0..15)
    const int am = t >> 2, ac = t & 3;     // A load mapping
    const int bk = t >> 4, bn4 = t & 15;   // B load mapping

    u64 acc[2][4];
#pragma unroll
    for (int i = 0; i < 2; ++i)
#pragma unroll
        for (int j = 0; j < 4; ++j) acc[i][j] = 0ull;

    const float* aBase = vfs + (size_t)(m0 + am) * DV + kb0 + ac * 4;
    const float* bBase = W1 + (size_t)(kb0 + bk) * DH + n0 + bn4 * 4;

    // prologue: load k-tile 0 into buffer 0
    {
        float4 av = *(const float4*)aBase;
        float4 wv = *(const float4*)bBase;
        As[0][ac * 4 + 0][am] = fmaxf(av.x, 0.f);
        As[0][ac * 4 + 1][am] = fmaxf(av.y, 0.f);
        As[0][ac * 4 + 2][am] = fmaxf(av.z, 0.f);
        As[0][ac * 4 + 3][am] = fmaxf(av.w, 0.f);
        Bs2[0][bk][bn4 * 4 + 0] = fpack(wv.x, wv.x);
        Bs2[0][bk][bn4 * 4 + 1] = fpack(wv.y, wv.y);
        Bs2[0][bk][bn4 * 4 + 2] = fpack(wv.z, wv.z);
        Bs2[0][bk][bn4 * 4 + 3] = fpack(wv.w, wv.w);
    }
    __syncthreads();

    for (int kt = 0; kt < 32; ++kt) {
        const int cur = kt & 1;
        const int nxt = cur ^ 1;

        float4 av_n, wv_n;
        if (kt < 31) {
            av_n = *(const float4*)(aBase + (kt + 1) * 16);
            wv_n = *(const float4*)(bBase + (size_t)(kt + 1) * 16 * DH);
        }

#pragma unroll
        for (int kk = 0; kk < 16; ++kk) {
            ulonglong2 ap  = *(const ulonglong2*)&As[cur][kk][ty * 4];
            ulonglong2 b01 = *(const ulonglong2*)&Bs2[cur][kk][tx * 2];
            ulonglong2 b23 = *(const ulonglong2*)&Bs2[cur][kk][32 + tx * 2];
            acc[0][0] = f2fma(ap.x, b01.x, acc[0][0]);
            acc[0][1] = f2fma(ap.x, b01.y, acc[0][1]);
            acc[0][2] = f2fma(ap.x, b23.x, acc[0][2]);
            acc[0][3] = f2fma(ap.x, b23.y, acc[0][3]);
            acc[1][0] = f2fma(ap.y, b01.x, acc[1][0]);
            acc[1][1] = f2fma(ap.y, b01.y, acc[1][1]);
            acc[1][2] = f2fma(ap.y, b23.x, acc[1][2]);
            acc[1][3] = f2fma(ap.y, b23.y, acc[1][3]);
        }

        if (kt < 31) {
            As[nxt][ac * 4 + 0][am] = fmaxf(av_n.x, 0.f);
            As[nxt][ac * 4 + 1][am] = fmaxf(av_n.y, 0.f);
            As[nxt][ac * 4 + 2][am] = fmaxf(av_n.z, 0.f);
            As[nxt][ac * 4 + 3][am] = fmaxf(av_n.w, 0.f);
            Bs2[nxt][bk][bn4 * 4 + 0] = fpack(wv_n.x, wv_n.x);
            Bs2[nxt][bk][bn4 * 4 + 1] = fpack(wv_n.y, wv_n.y);
            Bs2[nxt][bk][bn4 * 4 + 2] = fpack(wv_n.z, wv_n.z);
            Bs2[nxt][bk][bn4 * 4 + 3] = fpack(wv_n.w, wv_n.w);
        }
        __syncthreads();
    }

    // epilogue: n mapping j -> {tx*2, tx*2+1, tx*2+32, tx*2+33}
    float* outp = g_hp[blockIdx.z];
#pragma unroll
    for (int i = 0; i < 2; ++i)
#pragma unroll
        for (int j = 0; j < 4; ++j) {
            float2 v = funpack(acc[i][j]);
            int m = m0 + ty * 4 + i * 2;
            int n = n0 + ((j & 2) ? 32 : 0) + tx * 2 + (j & 1);
            outp[(size_t)m * DH + n]       = v.x;
            outp[(size_t)(m + 1) * DH + n] = v.y;
        }
}

// ---------------------------------------------------------------------------
// GEMM2: g_ep[s] = relu(sum_z g_hp[z] + b1) @ W2  over k-range of split s
// grid (16, 8) = 128 blocks
// ---------------------------------------------------------------------------
__global__ __launch_bounds__(256) void gemm2_kernel(
    const float* __restrict__ W2, const float* __restrict__ b1)
{
    __shared__ __align__(16) float sh_h[16 * 64];
    __shared__ float sh_w[64 * 112];

    const int t = threadIdx.x;
    const int m0  = blockIdx.x * 16;
    const int ks0 = blockIdx.y * 128;
    const int tm = t >> 4, tj = t & 15;

    float acc[7];
#pragma unroll
    for (int u = 0; u < 7; ++u) acc[u] = 0.f;

    for (int c = 0; c < 2; ++c) {
        const int kc = ks0 + c * 64;

        // h = relu(sum_z g_hp[z] + b1): 16x64 floats, 4 per thread
        {
            int idx = t * 4;
            int m = idx >> 6, kk = idx & 63;
            size_t off = (size_t)(m0 + m) * DH + kc + kk;
            float4 hv = *(const float4*)(b1 + kc + kk);
#pragma unroll
            for (int z = 0; z < SPL1; ++z) {
                float4 p = *(const float4*)(g_hp[z] + off);
                hv.x += p.x; hv.y += p.y; hv.z += p.z; hv.w += p.w;
            }
            hv.x = fmaxf(hv.x, 0.f);
            hv.y = fmaxf(hv.y, 0.f);
            hv.z = fmaxf(hv.z, 0.f);
            hv.w = fmaxf(hv.w, 0.f);
            *(float4*)&sh_h[m * 64 + kk] = hv;
        }
        // W2 chunk (64 x 100)
#pragma unroll
        for (int r = 0; r < 25; ++r) {
            int idx = r * 256 + t;
            int kk = idx / 100;
            int j  = idx - kk * 100;
            sh_w[kk * 112 + j] = W2[(size_t)(kc + kk) * DE + j];
        }
        __syncthreads();

#pragma unroll 8
        for (int kk = 0; kk < 64; ++kk) {
            float a = sh_h[tm * 64 + kk];
#pragma unroll
            for (int u = 0; u < 7; ++u)
                acc[u] += a * sh_w[kk * 112 + tj + 16 * u];
        }
        __syncthreads();
    }

    float* ep = g_ep[blockIdx.y];
#pragma unroll
    for (int u = 0; u < 7; ++u) {
        int j = tj + 16 * u;
        if (j < DE) ep[(size_t)(m0 + tm) * DE + j] = acc[u];
    }
}

// ---------------------------------------------------------------------------
// Scoring: out[n,l] = -sqrt( sum_d relu(lv[l,d] - e[n,d])^2 )
// ---------------------------------------------------------------------------
__global__ __launch_bounds__(256, 2) void score_kernel(
    const float* __restrict__ lv, const float* __restrict__ b2,
    float* __restrict__ out)
{
    __shared__ __align__(16) float e_s[16 * DE];

    const int t  = threadIdx.x;
    const int n0 = blockIdx.y * 16;

    for (int idx = t; idx < 16 * DE; idx += 256) {
        int n = idx / DE;
        int d = idx - n * DE;
        float v = b2[d];
#pragma unroll
        for (int s = 0; s < 8; ++s) v += g_ep[s][(size_t)(n0 + n) * DE + d];
        e_s[idx] = -v;
    }
    __syncthreads();

    const u64* es2 = (const u64*)e_s;

    const int l0 = blockIdx.x * 512 + t;
    const int l1 = l0 + 256;
    const int lc0 = min(l0, LL - 1);
    const int lc1 = min(l1, LL - 1);

    const ulonglong2* p0 = (const ulonglong2*)(lv + (size_t)lc0 * DE);
    const ulonglong2* p1 = (const ulonglong2*)(lv + (size_t)lc1 * DE);

    u64 acc0[16], acc1[16];
#pragma unroll
    for (int n = 0; n < 16; ++n) { acc0[n] = 0ull; acc1[n] = 0ull; }

    ulonglong2 a0 = p0[0], a1 = p1[0];

    for (int q = 0; q < 25; ++q) {
        const int qn = (q < 24) ? (q + 1) : 24;
        ulonglong2 na0 = p0[qn];
        ulonglong2 na1 = p1[qn];

        const int dp = q << 1;
#pragma unroll
        for (int n = 0; n < 16; ++n) {
            u64 e2 = es2[n * 50 + dp];
            u64 t0 = f2relu(f2add(a0.x, e2));
            acc0[n] = f2fma(t0, t0, acc0[n]);
            u64 t1 = f2relu(f2add(a1.x, e2));
            acc1[n] = f2fma(t1, t1, acc1[n]);
        }
#pragma unroll
        for (int n = 0; n < 16; ++n) {
            u64 e2 = es2[n * 50 + dp + 1];
            u64 t0 = f2relu(f2add(a0.y, e2));
            acc0[n] = f2fma(t0, t0, acc0[n]);
            u64 t1 = f2relu(f2add(a1.y, e2));
            acc1[n] = f2fma(t1, t1, acc1[n]);
        }
        a0 = na0; a1 = na1;
    }

    if (l0 < LL) {
#pragma unroll
        for (int n = 0; n < 16; ++n) {
            float2 v = funpack(acc0[n]);
            out[(size_t)(n0 + n) * LL + l0] = -fsqrt_ap(v.x + v.y);
        }
    }
    if (l1 < LL) {
#pragma unroll
        for (int n = 0; n < 16; ++n) {
            float2 v = funpack(acc1[n]);
            out[(size_t)(n0 + n) * LL + l1] = -fsqrt_ap(v.x + v.y);
        }
    }
}

// ---------------------------------------------------------------------------
extern "C" void kernel_launch(void* const* d_in, const int* in_sizes, int n_in,
                              void* d_out, int out_size)
{
    const float* vfs = (const float*)d_in[0];   // [256, 4096]
    const float* lv  = (const float*)d_in[1];   // [20000, 100]
    const float* W1  = (const float*)d_in[2];   // [4096, 1024]
    const float* b1  = (const float*)d_in[3];   // [1024]
    const float* W2  = (const float*)d_in[4];   // [1024, 100]
    const float* b2  = (const float*)d_in[5];   // [100]
    float* out = (float*)d_out;                 // [256, 20000]

    gemm1_kernel<<<dim3(16, 4, SPL1), 256>>>(vfs, W1);
    gemm2_kernel<<<dim3(16, 8), 256>>>(W2, b1);
    score_kernel<<<dim3(40, 16), 256>>>(lv, b2, out);
}

// round 4
// speedup vs baseline: 1.4826x; 1.4826x over previous
#include <cuda_runtime.h>
#include <cuda_bf16.h>

// ---------------------------------------------------------------------------
// HypernymVisual: h = relu(vfs)@W1 + b1 ; e = relu(h)@W2 + b2 ;
// scores[n,l] = -sqrt(sum_d relu(lv[l,d] - e[n,d])^2)
//
// Round 4: GEMM1 on tensor cores (mma.sync m16n8k16 bf16) with bf16 split-2
// error compensation (ah*bh + ah*bl + al*bh, fp32 accum -> ~1e-5 rel err).
// Prep kernels split relu(vfs) and transpose/split W1 once.
// ---------------------------------------------------------------------------

#define NV   256
#define DV   4096
#define DH   1024
#define DE   100
#define LL   20000
#define SPL1 4      // gemm1 K splits (1024 cols each)

typedef unsigned long long u64;

// scratch (device globals)
__device__ uint4 g_Ah4[NV * DV / 8];   // bf16 [256][4096]  hi(relu(vfs))
__device__ uint4 g_Al4[NV * DV / 8];   // bf16 [256][4096]  lo residual
__device__ uint4 g_Bh4[DH * DV / 8];   // bf16 [1024 n][4096 k]  hi(W1^T)
__device__ uint4 g_Bl4[DH * DV / 8];   // bf16 [1024 n][4096 k]  lo residual
__device__ float g_hp[SPL1][NV * DH];  // gemm1 K-split partials (no bias)
__device__ float g_ep[8][NV * DE];     // gemm2 K-split partials (no bias)

// ---- f32x2 helpers ---------------------------------------------------------
__device__ __forceinline__ u64 f2add(u64 a, u64 b) {
    u64 r; asm("add.rn.f32x2 %0,%1,%2;" : "=l"(r) : "l"(a), "l"(b)); return r;
}
__device__ __forceinline__ u64 f2fma(u64 a, u64 b, u64 c) {
    u64 r; asm("fma.rn.f32x2 %0,%1,%2,%3;" : "=l"(r) : "l"(a), "l"(b), "l"(c)); return r;
}
__device__ __forceinline__ u64 f2relu(u64 x) {
    u64 r;
    asm("{\n\t"
        ".reg .s32 lo, hi;\n\t"
        "mov.b64 {lo, hi}, %1;\n\t"
        "max.s32 lo, lo, 0;\n\t"
        "max.s32 hi, hi, 0;\n\t"
        "mov.b64 %0, {lo, hi};\n\t"
        "}" : "=l"(r) : "l"(x));
    return r;
}
__device__ __forceinline__ float2 funpack(u64 a) {
    unsigned lo, hi;
    asm("mov.b64 {%0,%1},%2;" : "=r"(lo), "=r"(hi) : "l"(a));
    return make_float2(__uint_as_float(lo), __uint_as_float(hi));
}
__device__ __forceinline__ float fsqrt_ap(float x) {
    float r; asm("sqrt.approx.f32 %0,%1;" : "=f"(r) : "f"(x)); return r;
}

// ---- bf16 mma --------------------------------------------------------------
__device__ __forceinline__ void mma_bf16(float d[4], const unsigned a[4],
                                         const unsigned b[2]) {
    asm("mma.sync.aligned.m16n8k16.row.col.f32.bf16.bf16.f32 "
        "{%0,%1,%2,%3},{%4,%5,%6,%7},{%8,%9},{%0,%1,%2,%3};"
        : "+f"(d[0]), "+f"(d[1]), "+f"(d[2]), "+f"(d[3])
        : "r"(a[0]), "r"(a[1]), "r"(a[2]), "r"(a[3]), "r"(b[0]), "r"(b[1]));
}

// ---------------------------------------------------------------------------
// prep_a: A = relu(vfs) -> bf16 hi/lo split, layout [m][k] (k contiguous)
// ---------------------------------------------------------------------------
__global__ __launch_bounds__(256) void prep_a(const float* __restrict__ vfs)
{
    int i = blockIdx.x * 256 + threadIdx.x;        // float4 index
    float4 v = ((const float4*)vfs)[i];
    v.x = fmaxf(v.x, 0.f); v.y = fmaxf(v.y, 0.f);
    v.z = fmaxf(v.z, 0.f); v.w = fmaxf(v.w, 0.f);
    __nv_bfloat16 h0 = __float2bfloat16(v.x);
    __nv_bfloat16 h1 = __float2bfloat16(v.y);
    __nv_bfloat16 h2 = __float2bfloat16(v.z);
    __nv_bfloat16 h3 = __float2bfloat16(v.w);
    __nv_bfloat16 l0 = __float2bfloat16(v.x - __bfloat162float(h0));
    __nv_bfloat16 l1 = __float2bfloat16(v.y - __bfloat162float(h1));
    __nv_bfloat16 l2 = __float2bfloat16(v.z - __bfloat162float(h2));
    __nv_bfloat16 l3 = __float2bfloat16(v.w - __bfloat162float(h3));
    __nv_bfloat162* ph = (__nv_bfloat162*)g_Ah4;
    __nv_bfloat162* pl = (__nv_bfloat162*)g_Al4;
    ph[i * 2 + 0] = __nv_bfloat162{h0, h1};
    ph[i * 2 + 1] = __nv_bfloat162{h2, h3};
    pl[i * 2 + 0] = __nv_bfloat162{l0, l1};
    pl[i * 2 + 1] = __nv_bfloat162{l2, l3};
}

// ---------------------------------------------------------------------------
// prep_bt: W1 [k=4096][n=1024] fp32 -> transposed bf16 hi/lo [n][k]
// ---------------------------------------------------------------------------
__global__ __launch_bounds__(256) void prep_bt(const float* __restrict__ W1)
{
    __shared__ float tile[32][33];
    const int k0 = blockIdx.x * 32, n0 = blockIdx.y * 32;
    const int t = threadIdx.x;
    const int nc = t & 31, kr0 = t >> 5;
#pragma unroll
    for (int i = 0; i < 4; ++i) {
        int kr = kr0 + i * 8;
        tile[kr][nc] = W1[(size_t)(k0 + kr) * DH + n0 + nc];
    }
    __syncthreads();
    const int i = t >> 3, j0 = (t & 7) * 4;
    __nv_bfloat16 hs[4], ls[4];
#pragma unroll
    for (int jj = 0; jj < 4; ++jj) {
        float x = tile[j0 + jj][i];
        __nv_bfloat16 h = __float2bfloat16(x);
        hs[jj] = h;
        ls[jj] = __float2bfloat16(x - __bfloat162float(h));
    }
    size_t off = (size_t)(n0 + i) * DV + k0 + j0;   // bf16 elements
    __nv_bfloat162* ph = (__nv_bfloat162*)((__nv_bfloat16*)g_Bh4 + off);
    __nv_bfloat162* pl = (__nv_bfloat162*)((__nv_bfloat16*)g_Bl4 + off);
    ph[0] = __nv_bfloat162{hs[0], hs[1]};
    ph[1] = __nv_bfloat162{hs[2], hs[3]};
    pl[0] = __nv_bfloat162{ls[0], ls[1]};
    pl[1] = __nv_bfloat162{ls[2], ls[3]};
}

// ---------------------------------------------------------------------------
// gemm1_tc: g_hp[z][m][n] = sum over K-slice of (ah+al)(bh+bl) (3 products)
// CTA tile M64 x N128, 8 warps (2m x 4n), warp tile 32x32, K chunk 32.
// grid (8 n, 4 m, SPL1 z) = 128 CTAs.
// ---------------------------------------------------------------------------
__global__ __launch_bounds__(256) void gemm1_tc(int dummy)
{
    __shared__ unsigned short sAh[64][40], sAl[64][40];
    __shared__ unsigned short sBh[128][40], sBl[128][40];

    const int t = threadIdx.x;
    const int lane = t & 31, warp = t >> 5;
    const int g = lane >> 2, tq = lane & 3;
    const int wm = warp & 1, wn = warp >> 1;
    const int m0 = blockIdx.y * 64, n0 = blockIdx.x * 128;
    const size_t kb0 = (size_t)blockIdx.z * 1024;

    const __nv_bfloat16* Ah = (const __nv_bfloat16*)g_Ah4;
    const __nv_bfloat16* Al = (const __nv_bfloat16*)g_Al4;
    const __nv_bfloat16* Bh = (const __nv_bfloat16*)g_Bh4;
    const __nv_bfloat16* Bl = (const __nv_bfloat16*)g_Bl4;

    const int ldRow  = t >> 2;            // 0..63
    const int ldPart = (t & 3) * 8;       // bf16 elems
    const size_t aOff  = (size_t)(m0 + ldRow) * DV + kb0 + ldPart;
    const size_t bOff1 = (size_t)(n0 + ldRow) * DV + kb0 + ldPart;
    const size_t bOff2 = (size_t)(n0 + 64 + ldRow) * DV + kb0 + ldPart;

    float d[2][4][4];
#pragma unroll
    for (int mf = 0; mf < 2; ++mf)
#pragma unroll
        for (int nf = 0; nf < 4; ++nf)
#pragma unroll
            for (int r = 0; r < 4; ++r) d[mf][nf][r] = 0.f;

    // prologue: chunk 0
    uint4 pAh = *(const uint4*)(Ah + aOff);
    uint4 pAl = *(const uint4*)(Al + aOff);
    uint4 pB1h = *(const uint4*)(Bh + bOff1);
    uint4 pB2h = *(const uint4*)(Bh + bOff2);
    uint4 pB1l = *(const uint4*)(Bl + bOff1);
    uint4 pB2l = *(const uint4*)(Bl + bOff2);
    *(uint4*)&sAh[ldRow][ldPart] = pAh;
    *(uint4*)&sAl[ldRow][ldPart] = pAl;
    *(uint4*)&sBh[ldRow][ldPart] = pB1h;
    *(uint4*)&sBh[64 + ldRow][ldPart] = pB2h;
    *(uint4*)&sBl[ldRow][ldPart] = pB1l;
    *(uint4*)&sBl[64 + ldRow][ldPart] = pB2l;
    __syncthreads();

    for (int c = 0; c < 32; ++c) {
        if (c < 31) {
            size_t kd = (size_t)(c + 1) * 32;
            pAh  = *(const uint4*)(Ah + aOff + kd);
            pAl  = *(const uint4*)(Al + aOff + kd);
            pB1h = *(const uint4*)(Bh + bOff1 + kd);
            pB2h = *(const uint4*)(Bh + bOff2 + kd);
            pB1l = *(const uint4*)(Bl + bOff1 + kd);
            pB2l = *(const uint4*)(Bl + bOff2 + kd);
        }

#pragma unroll
        for (int s = 0; s < 2; ++s) {
            const int kc = s * 16 + 2 * tq;
            unsigned ah[2][4], al[2][4];
#pragma unroll
            for (int mf = 0; mf < 2; ++mf) {
                int r = wm * 32 + mf * 16 + g;
                ah[mf][0] = *(const unsigned*)&sAh[r][kc];
                ah[mf][1] = *(const unsigned*)&sAh[r + 8][kc];
                ah[mf][2] = *(const unsigned*)&sAh[r][kc + 8];
                ah[mf][3] = *(const unsigned*)&sAh[r + 8][kc + 8];
                al[mf][0] = *(const unsigned*)&sAl[r][kc];
                al[mf][1] = *(const unsigned*)&sAl[r + 8][kc];
                al[mf][2] = *(const unsigned*)&sAl[r][kc + 8];
                al[mf][3] = *(const unsigned*)&sAl[r + 8][kc + 8];
            }
#pragma unroll
            for (int nf = 0; nf < 4; ++nf) {
                int n = wn * 32 + nf * 8 + g;
                unsigned bh[2], bl[2];
                bh[0] = *(const unsigned*)&sBh[n][kc];
                bh[1] = *(const unsigned*)&sBh[n][kc + 8];
                bl[0] = *(const unsigned*)&sBl[n][kc];
                bl[1] = *(const unsigned*)&sBl[n][kc + 8];
#pragma unroll
                for (int mf = 0; mf < 2; ++mf) {
                    mma_bf16(d[mf][nf], ah[mf], bh);
                    mma_bf16(d[mf][nf], ah[mf], bl);
                    mma_bf16(d[mf][nf], al[mf], bh);
                }
            }
        }
        __syncthreads();
        if (c < 31) {
            *(uint4*)&sAh[ldRow][ldPart] = pAh;
            *(uint4*)&sAl[ldRow][ldPart] = pAl;
            *(uint4*)&sBh[ldRow][ldPart] = pB1h;
            *(uint4*)&sBh[64 + ldRow][ldPart] = pB2h;
            *(uint4*)&sBl[ldRow][ldPart] = pB1l;
            *(uint4*)&sBl[64 + ldRow][ldPart] = pB2l;
            __syncthreads();
        }
    }

    float* outp = g_hp[blockIdx.z];
#pragma unroll
    for (int mf = 0; mf < 2; ++mf)
#pragma unroll
        for (int nf = 0; nf < 4; ++nf) {
            int m = m0 + wm * 32 + mf * 16 + g;
            int n = n0 + wn * 32 + nf * 8 + 2 * tq;
            *(float2*)&outp[(size_t)m * DH + n] =
                make_float2(d[mf][nf][0], d[mf][nf][1]);
            *(float2*)&outp[(size_t)(m + 8) * DH + n] =
                make_float2(d[mf][nf][2], d[mf][nf][3]);
        }
}

// ---------------------------------------------------------------------------
// GEMM2: g_ep[s] = relu(sum_z g_hp[z] + b1) @ W2  over k-range of split s
// grid (16, 8) = 128 blocks
// ---------------------------------------------------------------------------
__global__ __launch_bounds__(256) void gemm2_kernel(
    const float* __restrict__ W2, const float* __restrict__ b1)
{
    __shared__ __align__(16) float sh_h[16 * 64];
    __shared__ float sh_w[64 * 112];

    const int t = threadIdx.x;
    const int m0  = blockIdx.x * 16;
    const int ks0 = blockIdx.y * 128;
    const int tm = t >> 4, tj = t & 15;

    float acc[7];
#pragma unroll
    for (int u = 0; u < 7; ++u) acc[u] = 0.f;

    for (int c = 0; c < 2; ++c) {
        const int kc = ks0 + c * 64;
        {
            int idx = t * 4;
            int m = idx >> 6, kk = idx & 63;
            size_t off = (size_t)(m0 + m) * DH + kc + kk;
            float4 hv = *(const float4*)(b1 + kc + kk);
#pragma unroll
            for (int z = 0; z < SPL1; ++z) {
                float4 p = *(const float4*)(g_hp[z] + off);
                hv.x += p.x; hv.y += p.y; hv.z += p.z; hv.w += p.w;
            }
            hv.x = fmaxf(hv.x, 0.f);
            hv.y = fmaxf(hv.y, 0.f);
            hv.z = fmaxf(hv.z, 0.f);
            hv.w = fmaxf(hv.w, 0.f);
            *(float4*)&sh_h[m * 64 + kk] = hv;
        }
#pragma unroll
        for (int r = 0; r < 25; ++r) {
            int idx = r * 256 + t;
            int kk = idx / 100;
            int j  = idx - kk * 100;
            sh_w[kk * 112 + j] = W2[(size_t)(kc + kk) * DE + j];
        }
        __syncthreads();

#pragma unroll 8
        for (int kk = 0; kk < 64; ++kk) {
            float a = sh_h[tm * 64 + kk];
#pragma unroll
            for (int u = 0; u < 7; ++u)
                acc[u] += a * sh_w[kk * 112 + tj + 16 * u];
        }
        __syncthreads();
    }

    float* ep = g_ep[blockIdx.y];
#pragma unroll
    for (int u = 0; u < 7; ++u) {
        int j = tj + 16 * u;
        if (j < DE) ep[(size_t)(m0 + tm) * DE + j] = acc[u];
    }
}

// ---------------------------------------------------------------------------
// Scoring: out[n,l] = -sqrt( sum_d relu(lv[l,d] - e[n,d])^2 )
// ---------------------------------------------------------------------------
__global__ __launch_bounds__(256, 2) void score_kernel(
    const float* __restrict__ lv, const float* __restrict__ b2,
    float* __restrict__ out)
{
    __shared__ __align__(16) float e_s[16 * DE];

    const int t  = threadIdx.x;
    const int n0 = blockIdx.y * 16;

    for (int idx = t; idx < 16 * DE; idx += 256) {
        int n = idx / DE;
        int d = idx - n * DE;
        float v = b2[d];
#pragma unroll
        for (int s = 0; s < 8; ++s) v += g_ep[s][(size_t)(n0 + n) * DE + d];
        e_s[idx] = -v;
    }
    __syncthreads();

    const u64* es2 = (const u64*)e_s;

    const int l0 = blockIdx.x * 512 + t;
    const int l1 = l0 + 256;
    const int lc0 = min(l0, LL - 1);
    const int lc1 = min(l1, LL - 1);

    const ulonglong2* p0 = (const ulonglong2*)(lv + (size_t)lc0 * DE);
    const ulonglong2* p1 = (const ulonglong2*)(lv + (size_t)lc1 * DE);

    u64 acc0[16], acc1[16];
#pragma unroll
    for (int n = 0; n < 16; ++n) { acc0[n] = 0ull; acc1[n] = 0ull; }

    ulonglong2 a0 = p0[0], a1 = p1[0];

    for (int q = 0; q < 25; ++q) {
        const int qn = (q < 24) ? (q + 1) : 24;
        ulonglong2 na0 = p0[qn];
        ulonglong2 na1 = p1[qn];

        const int dp = q << 1;
#pragma unroll
        for (int n = 0; n < 16; ++n) {
            u64 e2 = es2[n * 50 + dp];
            u64 t0 = f2relu(f2add(a0.x, e2));
            acc0[n] = f2fma(t0, t0, acc0[n]);
            u64 t1 = f2relu(f2add(a1.x, e2));
            acc1[n] = f2fma(t1, t1, acc1[n]);
        }
#pragma unroll
        for (int n = 0; n < 16; ++n) {
            u64 e2 = es2[n * 50 + dp + 1];
            u64 t0 = f2relu(f2add(a0.y, e2));
            acc0[n] = f2fma(t0, t0, acc0[n]);
            u64 t1 = f2relu(f2add(a1.y, e2));
            acc1[n] = f2fma(t1, t1, acc1[n]);
        }
        a0 = na0; a1 = na1;
    }

    if (l0 < LL) {
#pragma unroll
        for (int n = 0; n < 16; ++n) {
            float2 v = funpack(acc0[n]);
            out[(size_t)(n0 + n) * LL + l0] = -fsqrt_ap(v.x + v.y);
        }
    }
    if (l1 < LL) {
#pragma unroll
        for (int n = 0; n < 16; ++n) {
            float2 v = funpack(acc1[n]);
            out[(size_t)(n0 + n) * LL + l1] = -fsqrt_ap(v.x + v.y);
        }
    }
}

// ---------------------------------------------------------------------------
extern "C" void kernel_launch(void* const* d_in, const int* in_sizes, int n_in,
                              void* d_out, int out_size)
{
    const float* vfs = (const float*)d_in[0];   // [256, 4096]
    const float* lv  = (const float*)d_in[1];   // [20000, 100]
    const float* W1  = (const float*)d_in[2];   // [4096, 1024]
    const float* b1  = (const float*)d_in[3];   // [1024]
    const float* W2  = (const float*)d_in[4];   // [1024, 100]
    const float* b2  = (const float*)d_in[5];   // [100]
    float* out = (float*)d_out;                 // [256, 20000]

    prep_a<<<NV * DV / 4 / 256, 256>>>(vfs);
    prep_bt<<<dim3(DV / 32, DH / 32), 256>>>(W1);
    gemm1_tc<<<dim3(8, 4, SPL1), 256>>>(0);
    gemm2_kernel<<<dim3(16, 8), 256>>>(W2, b1);
    score_kernel<<<dim3(40, 16), 256>>>(lv, b2, out);
}

// round 5
// speedup vs baseline: 1.6225x; 1.0943x over previous
#include <cuda_runtime.h>
#include <cuda_bf16.h>

// ---------------------------------------------------------------------------
// HypernymVisual: h = relu(vfs)@W1 + b1 ; e = relu(h)@W2 + b2 ;
// scores[n,l] = -sqrt(sum_d relu(lv[l,d] - e[n,d])^2)
//
// Round 5: gemm1_tc occupancy (SPL1=8, 256 CTAs), product-major MMA ordering
// (dep distance 8), single barrier per chunk; merged prep kernel; score uses
// LDS.128 for e-pairs.
// ---------------------------------------------------------------------------

#define NV   256
#define DV   4096
#define DH   1024
#define DE   100
#define LL   20000
#define SPL1 8      // gemm1 K splits (512 cols each)

typedef unsigned long long u64;

// scratch (device globals)
__device__ uint4 g_Ah4[NV * DV / 8];   // bf16 [256][4096]  hi(relu(vfs))
__device__ uint4 g_Al4[NV * DV / 8];   // bf16 [256][4096]  lo residual
__device__ uint4 g_Bh4[DH * DV / 8];   // bf16 [1024 n][4096 k]  hi(W1^T)
__device__ uint4 g_Bl4[DH * DV / 8];   // bf16 [1024 n][4096 k]  lo residual
__device__ float g_hp[SPL1][NV * DH];  // gemm1 K-split partials (no bias)
__device__ float g_ep[8][NV * DE];     // gemm2 K-split partials (no bias)

// ---- f32x2 helpers ---------------------------------------------------------
__device__ __forceinline__ u64 f2add(u64 a, u64 b) {
    u64 r; asm("add.rn.f32x2 %0,%1,%2;" : "=l"(r) : "l"(a), "l"(b)); return r;
}
__device__ __forceinline__ u64 f2fma(u64 a, u64 b, u64 c) {
    u64 r; asm("fma.rn.f32x2 %0,%1,%2,%3;" : "=l"(r) : "l"(a), "l"(b), "l"(c)); return r;
}
__device__ __forceinline__ u64 f2relu(u64 x) {
    u64 r;
    asm("{\n\t"
        ".reg .s32 lo, hi;\n\t"
        "mov.b64 {lo, hi}, %1;\n\t"
        "max.s32 lo, lo, 0;\n\t"
        "max.s32 hi, hi, 0;\n\t"
        "mov.b64 %0, {lo, hi};\n\t"
        "}" : "=l"(r) : "l"(x));
    return r;
}
__device__ __forceinline__ float2 funpack(u64 a) {
    unsigned lo, hi;
    asm("mov.b64 {%0,%1},%2;" : "=r"(lo), "=r"(hi) : "l"(a));
    return make_float2(__uint_as_float(lo), __uint_as_float(hi));
}
__device__ __forceinline__ float fsqrt_ap(float x) {
    float r; asm("sqrt.approx.f32 %0,%1;" : "=f"(r) : "f"(x)); return r;
}

// ---- bf16 mma --------------------------------------------------------------
__device__ __forceinline__ void mma_bf16(float d[4], const unsigned a[4],
                                         const unsigned b[2]) {
    asm("mma.sync.aligned.m16n8k16.row.col.f32.bf16.bf16.f32 "
        "{%0,%1,%2,%3},{%4,%5,%6,%7},{%8,%9},{%0,%1,%2,%3};"
        : "+f"(d[0]), "+f"(d[1]), "+f"(d[2]), "+f"(d[3])
        : "r"(a[0]), "r"(a[1]), "r"(a[2]), "r"(a[3]), "r"(b[0]), "r"(b[1]));
}

// ---------------------------------------------------------------------------
// prep_all: blocks [0,1024): A = relu(vfs) -> bf16 hi/lo, [m][k]
//           blocks [1024,5120): W1 -> transposed bf16 hi/lo [n][k]
// ---------------------------------------------------------------------------
__global__ __launch_bounds__(256) void prep_all(
    const float* __restrict__ vfs, const float* __restrict__ W1)
{
    if (blockIdx.x < 1024) {
        int i = blockIdx.x * 256 + threadIdx.x;        // float4 index
        float4 v = ((const float4*)vfs)[i];
        v.x = fmaxf(v.x, 0.f); v.y = fmaxf(v.y, 0.f);
        v.z = fmaxf(v.z, 0.f); v.w = fmaxf(v.w, 0.f);
        __nv_bfloat16 h0 = __float2bfloat16(v.x);
        __nv_bfloat16 h1 = __float2bfloat16(v.y);
        __nv_bfloat16 h2 = __float2bfloat16(v.z);
        __nv_bfloat16 h3 = __float2bfloat16(v.w);
        __nv_bfloat16 l0 = __float2bfloat16(v.x - __bfloat162float(h0));
        __nv_bfloat16 l1 = __float2bfloat16(v.y - __bfloat162float(h1));
        __nv_bfloat16 l2 = __float2bfloat16(v.z - __bfloat162float(h2));
        __nv_bfloat16 l3 = __float2bfloat16(v.w - __bfloat162float(h3));
        __nv_bfloat162* ph = (__nv_bfloat162*)g_Ah4;
        __nv_bfloat162* pl = (__nv_bfloat162*)g_Al4;
        ph[i * 2 + 0] = __nv_bfloat162{h0, h1};
        ph[i * 2 + 1] = __nv_bfloat162{h2, h3};
        pl[i * 2 + 0] = __nv_bfloat162{l0, l1};
        pl[i * 2 + 1] = __nv_bfloat162{l2, l3};
    } else {
        __shared__ float tile[32][33];
        const int bx = blockIdx.x - 1024;
        const int k0 = (bx & 127) * 32, n0 = (bx >> 7) * 32;
        const int t = threadIdx.x;
        const int nc = t & 31, kr0 = t >> 5;
#pragma unroll
        for (int i = 0; i < 4; ++i) {
            int kr = kr0 + i * 8;
            tile[kr][nc] = W1[(size_t)(k0 + kr) * DH + n0 + nc];
        }
        __syncthreads();
        const int i = t >> 3, j0 = (t & 7) * 4;
        __nv_bfloat16 hs[4], ls[4];
#pragma unroll
        for (int jj = 0; jj < 4; ++jj) {
            float x = tile[j0 + jj][i];
            __nv_bfloat16 h = __float2bfloat16(x);
            hs[jj] = h;
            ls[jj] = __float2bfloat16(x - __bfloat162float(h));
        }
        size_t off = (size_t)(n0 + i) * DV + k0 + j0;
        __nv_bfloat162* ph = (__nv_bfloat162*)((__nv_bfloat16*)g_Bh4 + off);
        __nv_bfloat162* pl = (__nv_bfloat162*)((__nv_bfloat16*)g_Bl4 + off);
        ph[0] = __nv_bfloat162{hs[0], hs[1]};
        ph[1] = __nv_bfloat162{hs[2], hs[3]};
        pl[0] = __nv_bfloat162{ls[0], ls[1]};
        pl[1] = __nv_bfloat162{ls[2], ls[3]};
    }
}

// ---------------------------------------------------------------------------
// gemm1_tc: g_hp[z][m][n] = A_slice @ B_slice with bf16 split-2 compensation
// CTA tile M64 x N128, 8 warps (2m x 4n), warp tile 32x32, K chunk 32.
// grid (8 n, 4 m, SPL1=8 z) = 256 CTAs; K-slice 512 = 16 chunks.
// ---------------------------------------------------------------------------
__global__ __launch_bounds__(256, 2) void gemm1_tc(int dummy)
{
    __shared__ unsigned short sAh[2][64][40], sAl[2][64][40];
    __shared__ unsigned short sBh[2][128][40], sBl[2][128][40];

    const int t = threadIdx.x;
    const int lane = t & 31, warp = t >> 5;
    const int g = lane >> 2, tq = lane & 3;
    const int wm = warp & 1, wn = warp >> 1;
    const int m0 = blockIdx.y * 64, n0 = blockIdx.x * 128;
    const size_t kb0 = (size_t)blockIdx.z * 512;

    const __nv_bfloat16* Ah = (const __nv_bfloat16*)g_Ah4;
    const __nv_bfloat16* Al = (const __nv_bfloat16*)g_Al4;
    const __nv_bfloat16* Bh = (const __nv_bfloat16*)g_Bh4;
    const __nv_bfloat16* Bl = (const __nv_bfloat16*)g_Bl4;

    const int ldRow  = t >> 2;            // 0..63
    const int ldPart = (t & 3) * 8;       // bf16 elems
    const size_t aOff  = (size_t)(m0 + ldRow) * DV + kb0 + ldPart;
    const size_t bOff1 = (size_t)(n0 + ldRow) * DV + kb0 + ldPart;
    const size_t bOff2 = (size_t)(n0 + 64 + ldRow) * DV + kb0 + ldPart;

    float d[2][4][4];
#pragma unroll
    for (int mf = 0; mf < 2; ++mf)
#pragma unroll
        for (int nf = 0; nf < 4; ++nf)
#pragma unroll
            for (int r = 0; r < 4; ++r) d[mf][nf][r] = 0.f;

    // prologue: chunk 0 -> buffer 0
    {
        uint4 pAh  = *(const uint4*)(Ah + aOff);
        uint4 pAl  = *(const uint4*)(Al + aOff);
        uint4 pB1h = *(const uint4*)(Bh + bOff1);
        uint4 pB2h = *(const uint4*)(Bh + bOff2);
        uint4 pB1l = *(const uint4*)(Bl + bOff1);
        uint4 pB2l = *(const uint4*)(Bl + bOff2);
        *(uint4*)&sAh[0][ldRow][ldPart] = pAh;
        *(uint4*)&sAl[0][ldRow][ldPart] = pAl;
        *(uint4*)&sBh[0][ldRow][ldPart] = pB1h;
        *(uint4*)&sBh[0][64 + ldRow][ldPart] = pB2h;
        *(uint4*)&sBl[0][ldRow][ldPart] = pB1l;
        *(uint4*)&sBl[0][64 + ldRow][ldPart] = pB2l;
    }
    __syncthreads();

    for (int c = 0; c < 16; ++c) {
        const int cur = c & 1;
        const int nxt = cur ^ 1;

        uint4 pAh, pAl, pB1h, pB2h, pB1l, pB2l;
        if (c < 15) {
            size_t kd = (size_t)(c + 1) * 32;
            pAh  = *(const uint4*)(Ah + aOff + kd);
            pAl  = *(const uint4*)(Al + aOff + kd);
            pB1h = *(const uint4*)(Bh + bOff1 + kd);
            pB2h = *(const uint4*)(Bh + bOff2 + kd);
            pB1l = *(const uint4*)(Bl + bOff1 + kd);
            pB2l = *(const uint4*)(Bl + bOff2 + kd);
        }

#pragma unroll
        for (int s = 0; s < 2; ++s) {
            const int kc = s * 16 + 2 * tq;
            unsigned ah[2][4], al[2][4], bh[4][2], bl[4][2];
#pragma unroll
            for (int mf = 0; mf < 2; ++mf) {
                int r = wm * 32 + mf * 16 + g;
                ah[mf][0] = *(const unsigned*)&sAh[cur][r][kc];
                ah[mf][1] = *(const unsigned*)&sAh[cur][r + 8][kc];
                ah[mf][2] = *(const unsigned*)&sAh[cur][r][kc + 8];
                ah[mf][3] = *(const unsigned*)&sAh[cur][r + 8][kc + 8];
                al[mf][0] = *(const unsigned*)&sAl[cur][r][kc];
                al[mf][1] = *(const unsigned*)&sAl[cur][r + 8][kc];
                al[mf][2] = *(const unsigned*)&sAl[cur][r][kc + 8];
                al[mf][3] = *(const unsigned*)&sAl[cur][r + 8][kc + 8];
            }
#pragma unroll
            for (int nf = 0; nf < 4; ++nf) {
                int n = wn * 32 + nf * 8 + g;
                bh[nf][0] = *(const unsigned*)&sBh[cur][n][kc];
                bh[nf][1] = *(const unsigned*)&sBh[cur][n][kc + 8];
                bl[nf][0] = *(const unsigned*)&sBl[cur][n][kc];
                bl[nf][1] = *(const unsigned*)&sBl[cur][n][kc + 8];
            }
            // product-major: consecutive MMAs hit distinct accumulators
#pragma unroll
            for (int nf = 0; nf < 4; ++nf)
#pragma unroll
                for (int mf = 0; mf < 2; ++mf)
                    mma_bf16(d[mf][nf], ah[mf], bh[nf]);
#pragma unroll
            for (int nf = 0; nf < 4; ++nf)
#pragma unroll
                for (int mf = 0; mf < 2; ++mf)
                    mma_bf16(d[mf][nf], ah[mf], bl[nf]);
#pragma unroll
            for (int nf = 0; nf < 4; ++nf)
#pragma unroll
                for (int mf = 0; mf < 2; ++mf)
                    mma_bf16(d[mf][nf], al[mf], bh[nf]);
        }

        if (c < 15) {
            *(uint4*)&sAh[nxt][ldRow][ldPart] = pAh;
            *(uint4*)&sAl[nxt][ldRow][ldPart] = pAl;
            *(uint4*)&sBh[nxt][ldRow][ldPart] = pB1h;
            *(uint4*)&sBh[nxt][64 + ldRow][ldPart] = pB2h;
            *(uint4*)&sBl[nxt][ldRow][ldPart] = pB1l;
            *(uint4*)&sBl[nxt][64 + ldRow][ldPart] = pB2l;
        }
        __syncthreads();
    }

    float* outp = g_hp[blockIdx.z];
#pragma unroll
    for (int mf = 0; mf < 2; ++mf)
#pragma unroll
        for (int nf = 0; nf < 4; ++nf) {
            int m = m0 + wm * 32 + mf * 16 + g;
            int n = n0 + wn * 32 + nf * 8 + 2 * tq;
            *(float2*)&outp[(size_t)m * DH + n] =
                make_float2(d[mf][nf][0], d[mf][nf][1]);
            *(float2*)&outp[(size_t)(m + 8) * DH + n] =
                make_float2(d[mf][nf][2], d[mf][nf][3]);
        }
}

// ---------------------------------------------------------------------------
// GEMM2: g_ep[s] = relu(sum_z g_hp[z] + b1) @ W2  over k-range of split s
// grid (16, 8) = 128 blocks
// ---------------------------------------------------------------------------
__global__ __launch_bounds__(256) void gemm2_kernel(
    const float* __restrict__ W2, const float* __restrict__ b1)
{
    __shared__ __align__(16) float sh_h[16 * 64];
    __shared__ float sh_w[64 * 112];

    const int t = threadIdx.x;
    const int m0  = blockIdx.x * 16;
    const int ks0 = blockIdx.y * 128;
    const int tm = t >> 4, tj = t & 15;

    float acc[7];
#pragma unroll
    for (int u = 0; u < 7; ++u) acc[u] = 0.f;

    for (int c = 0; c < 2; ++c) {
        const int kc = ks0 + c * 64;
        {
            int idx = t * 4;
            int m = idx >> 6, kk = idx & 63;
            size_t off = (size_t)(m0 + m) * DH + kc + kk;
            float4 hv = *(const float4*)(b1 + kc + kk);
#pragma unroll
            for (int z = 0; z < SPL1; ++z) {
                float4 p = *(const float4*)(g_hp[z] + off);
                hv.x += p.x; hv.y += p.y; hv.z += p.z; hv.w += p.w;
            }
            hv.x = fmaxf(hv.x, 0.f);
            hv.y = fmaxf(hv.y, 0.f);
            hv.z = fmaxf(hv.z, 0.f);
            hv.w = fmaxf(hv.w, 0.f);
            *(float4*)&sh_h[m * 64 + kk] = hv;
        }
#pragma unroll
        for (int r = 0; r < 25; ++r) {
            int idx = r * 256 + t;
            int kk = idx / 100;
            int j  = idx - kk * 100;
            sh_w[kk * 112 + j] = W2[(size_t)(kc + kk) * DE + j];
        }
        __syncthreads();

#pragma unroll 8
        for (int kk = 0; kk < 64; ++kk) {
            float a = sh_h[tm * 64 + kk];
#pragma unroll
            for (int u = 0; u < 7; ++u)
                acc[u] += a * sh_w[kk * 112 + tj + 16 * u];
        }
        __syncthreads();
    }

    float* ep = g_ep[blockIdx.y];
#pragma unroll
    for (int u = 0; u < 7; ++u) {
        int j = tj + 16 * u;
        if (j < DE) ep[(size_t)(m0 + tm) * DE + j] = acc[u];
    }
}

// ---------------------------------------------------------------------------
// Scoring: out[n,l] = -sqrt( sum_d relu(lv[l,d] - e[n,d])^2 )
// ---------------------------------------------------------------------------
__global__ __launch_bounds__(256, 2) void score_kernel(
    const float* __restrict__ lv, const float* __restrict__ b2,
    float* __restrict__ out)
{
    __shared__ __align__(16) float e_s[16 * DE];

    const int t  = threadIdx.x;
    const int n0 = blockIdx.y * 16;

    for (int idx = t; idx < 16 * DE; idx += 256) {
        int n = idx / DE;
        int d = idx - n * DE;
        float v = b2[d];
#pragma unroll
        for (int s = 0; s < 8; ++s) v += g_ep[s][(size_t)(n0 + n) * DE + d];
        e_s[idx] = -v;
    }
    __syncthreads();

    const u64* es2 = (const u64*)e_s;

    const int l0 = blockIdx.x * 512 + t;
    const int l1 = l0 + 256;
    const int lc0 = min(l0, LL - 1);
    const int lc1 = min(l1, LL - 1);

    const ulonglong2* p0 = (const ulonglong2*)(lv + (size_t)lc0 * DE);
    const ulonglong2* p1 = (const ulonglong2*)(lv + (size_t)lc1 * DE);

    u64 acc0[16], acc1[16];
#pragma unroll
    for (int n = 0; n < 16; ++n) { acc0[n] = 0ull; acc1[n] = 0ull; }

    ulonglong2 a0 = p0[0], a1 = p1[0];

    for (int q = 0; q < 25; ++q) {
        const int qn = (q < 24) ? (q + 1) : 24;
        ulonglong2 na0 = p0[qn];
        ulonglong2 na1 = p1[qn];

        const int dp = q << 1;
#pragma unroll
        for (int n = 0; n < 16; ++n) {
            ulonglong2 e4 = *(const ulonglong2*)&es2[n * 50 + dp];  // LDS.128
            u64 t0 = f2relu(f2add(a0.x, e4.x));
            acc0[n] = f2fma(t0, t0, acc0[n]);
            u64 t1 = f2relu(f2add(a1.x, e4.x));
            acc1[n] = f2fma(t1, t1, acc1[n]);
            u64 t2 = f2relu(f2add(a0.y, e4.y));
            acc0[n] = f2fma(t2, t2, acc0[n]);
            u64 t3 = f2relu(f2add(a1.y, e4.y));
            acc1[n] = f2fma(t3, t3, acc1[n]);
        }
        a0 = na0; a1 = na1;
    }

    if (l0 < LL) {
#pragma unroll
        for (int n = 0; n < 16; ++n) {
            float2 v = funpack(acc0[n]);
            out[(size_t)(n0 + n) * LL + l0] = -fsqrt_ap(v.x + v.y);
        }
    }
    if (l1 < LL) {
#pragma unroll
        for (int n = 0; n < 16; ++n) {
            float2 v = funpack(acc1[n]);
            out[(size_t)(n0 + n) * LL + l1] = -fsqrt_ap(v.x + v.y);
        }
    }
}

// ---------------------------------------------------------------------------
extern "C" void kernel_launch(void* const* d_in, const int* in_sizes, int n_in,
                              void* d_out, int out_size)
{
    const float* vfs = (const float*)d_in[0];   // [256, 4096]
    const float* lv  = (const float*)d_in[1];   // [20000, 100]
    const float* W1  = (const float*)d_in[2];   // [4096, 1024]
    const float* b1  = (const float*)d_in[3];   // [1024]
    const float* W2  = (const float*)d_in[4];   // [1024, 100]
    const float* b2  = (const float*)d_in[5];   // [100]
    float* out = (float*)d_out;                 // [256, 20000]

    prep_all<<<1024 + 4096, 256>>>(vfs, W1);
    gemm1_tc<<<dim3(8, 4, SPL1), 256>>>(0);
    gemm2_kernel<<<dim3(16, 8), 256>>>(W2, b1);
    score_kernel<<<dim3(40, 16), 256>>>(lv, b2, out);
}